// round 11
// baseline (speedup 1.0000x reference)
#include <cuda_runtime.h>
#include <cuda_fp16.h>
#include <math.h>
#include <stdint.h>

#define L_LAYERS 250
#define N_TRACES 600
#define N_THETA  30
#define NI   249                 // interfaces (ref row 249 is zero)
#define KPAD 256                 // padded K

// W fp16 plane (m-major, 256x256, zero padded). Written by zoe_wsplit each
// launch (deterministic); rows/cols >= 250 written as zeros.
__device__ __half g_Wh[256 * 256];

__device__ __forceinline__ float sqrt_approx(float x) {
    float r;
    asm("sqrt.approx.f32 %0, %1;" : "=f"(r) : "f"(x));
    return r;
}

// ---------------------------------------------------------------------------
// W split: W[l, k] (250x250 f32) -> 256x256 fp16 (zero padded)
// ---------------------------------------------------------------------------
__global__ void zoe_wsplit(const float* __restrict__ W) {
    int idx = blockIdx.x * 256 + threadIdx.x;
    if (idx >= 256 * 256) return;
    int r = idx >> 8, k = idx & 255;
    float v = (r < L_LAYERS && k < L_LAYERS) ? W[r * L_LAYERS + k] : 0.f;
    g_Wh[idx] = __float2half(v);
}

// ---------------------------------------------------------------------------
// Fused kernel: one block per 2 traces.
//  Stage A: compute Zoeppritz Rpp (Aki & Richards closed form, exact for these
//           input ranges) for both traces directly into smem as fp16
//           [k=256 rows][64 cols: trace0 angles 0-29 @0, trace1 @32; pads 0].
//  Stage B: HMMA GEMM out[t,l,a] = sum_k W[l,k] * R[k, ...]:
//           M=256, N=64, K=256. 8 warps (4m x 2n), warp tile 64x32,
//           m16n8k16, A streamed from g_Wh via 3-stage cp.async (8 k-steps of
//           BK=32, fully unrolled so s%3 and all smem offsets are constants),
//           B straight from the block-local Rs (no staging).
// ---------------------------------------------------------------------------
#define ABK 32
#define APITCH 40                       // 32 + 8 pad halves (80B rows)
#define RPITCH 72                       // 64 + 8 pad halves (144B rows)
#define ASTG (256 * APITCH)             // 10240 halves per A stage
#define RS_HALVES (256 * RPITCH)        // 18432 halves
#define SMEM_BYTES ((3 * ASTG + RS_HALVES) * 2 + 256)   // 98560

__device__ __forceinline__ uint32_t smaddr(const void* p) {
    return (uint32_t)__cvta_generic_to_shared(p);
}
__device__ __forceinline__ void ldsm4(uint32_t a[4], uint32_t addr) {
    asm volatile("ldmatrix.sync.aligned.m8n8.x4.shared.b16 {%0,%1,%2,%3}, [%4];"
                 : "=r"(a[0]), "=r"(a[1]), "=r"(a[2]), "=r"(a[3]) : "r"(addr));
}
__device__ __forceinline__ void ldsm4t(uint32_t a[4], uint32_t addr) {
    asm volatile("ldmatrix.sync.aligned.m8n8.x4.trans.shared.b16 {%0,%1,%2,%3}, [%4];"
                 : "=r"(a[0]), "=r"(a[1]), "=r"(a[2]), "=r"(a[3]) : "r"(addr));
}
__device__ __forceinline__ void mma16816(float c[4], const uint32_t a[4], const uint32_t b[2]) {
    asm volatile("mma.sync.aligned.m16n8k16.row.col.f32.f16.f16.f32 "
                 "{%0,%1,%2,%3}, {%4,%5,%6,%7}, {%8,%9}, {%0,%1,%2,%3};"
                 : "+f"(c[0]), "+f"(c[1]), "+f"(c[2]), "+f"(c[3])
                 : "r"(a[0]), "r"(a[1]), "r"(a[2]), "r"(a[3]), "r"(b[0]), "r"(b[1]));
}
#define CP16(dst, src) \
    asm volatile("cp.async.ca.shared.global [%0], [%1], 16;" :: "r"(dst), "l"(src))
#define CP_COMMIT() asm volatile("cp.async.commit_group;")
#define CP_WAIT(n)  asm volatile("cp.async.wait_group %0;" :: "n"(n))

__global__ __launch_bounds__(256, 2)
void zoe_fused(const float* __restrict__ vp,
               const float* __restrict__ vs,
               const float* __restrict__ rho,
               const float* __restrict__ theta,
               float* __restrict__ out) {
    extern __shared__ __half sm[];
    __half* Ah = sm;                         // 3 * ASTG halves
    __half* Rs = sm + 3 * ASTG;              // RS_HALVES halves
    float*  s_sc = (float*)(Rs + RS_HALVES); // [0..29] sin, [32..61] cos

    int tid = threadIdx.x;
    int t0  = blockIdx.x * 2;

    // ---- A prologue: issue stages 0..1 ASAP (overlap with phase-1 math).
    //      Stage 2 is issued by the s=0 refill inside the GEMM loop. ----
    const __half* pW = &g_Wh[tid * 256];         // row = tid
    uint32_t sA = smaddr(&Ah[tid * APITCH]);
#pragma unroll
    for (int s = 0; s < 2; s++) {
#pragma unroll
        for (int c = 0; c < 4; c++)
            CP16(sA + s * (ASTG * 2) + c * 16, pW + s * ABK + c * 8);
        CP_COMMIT();
    }

    // ---- sincos + Rs zero-fill ----
    if (tid < N_THETA) {
        float sv, cv;
        sincosf(theta[tid], &sv, &cv);
        s_sc[tid] = sv;
        s_sc[32 + tid] = cv;
    }
    {
        uint4 z = make_uint4(0, 0, 0, 0);
        uint4* r4 = (uint4*)Rs;
        const int NV = RS_HALVES * 2 / 16;       // 2304
#pragma unroll
        for (int i = 0; i < (NV + 255) / 256; i++) {
            int e = tid + i * 256;
            if (e < NV) r4[e] = z;
        }
    }
    __syncthreads();

    // ---- Phase 1: Zoeppritz Rpp into Rs ----
    // 498 (l, trace) pairs; thread handles p = tid, tid+256.
    for (int p = tid; p < 2 * NI; p += 256) {
        int j = (p >= NI) ? 1 : 0;
        int l = p - NI * j;
        int t = t0 + j;

        float a1 = vp[l * N_TRACES + t],  a2 = vp[(l + 1) * N_TRACES + t];
        float b1 = vs[l * N_TRACES + t],  b2 = vs[(l + 1) * N_TRACES + t];
        float r1 = rho[l * N_TRACES + t], r2 = rho[(l + 1) * N_TRACES + t];

        float inva1 = __fdividef(1.f, a1);
        float k1 = 2.f * r1 * (b1 * b1);
        float k2 = 2.f * r2 * (b2 * b2);
        float d  = k2 - k1;
        float drho = r2 - r1;
        float a1b2 = a1 * b2;
        float a2b1 = a2 * b1;

        __half* row = &Rs[l * RPITCH + j * 32];
#pragma unroll 6
        for (int a = 0; a < N_THETA; a++) {
            float sth = s_sc[a], cth = s_sc[32 + a];
            float pr  = sth * inva1;
            float p2 = pr * pr;

            float st2 = pr * a2;
            float ct2 = sqrt_approx(fmaxf(1.f - st2 * st2, 0.f));
            float sp1 = pr * b1;
            float cp1 = sqrt_approx(fmaxf(1.f - sp1 * sp1, 0.f));
            float sp2 = pr * b2;
            float cp2 = sqrt_approx(fmaxf(1.f - sp2 * sp2, 0.f));

            float dp2 = d * p2;
            float A = drho - dp2;
            float B = r2 - dp2;
            float C = r1 + dp2;

            float X = B * cth * a2;
            float Y = C * ct2 * a1;
            float E = X + Y;
            float F = fmaf(B * cp1, b2, C * cp2 * b1);
            float Z = d * cth * cp2;
            float Aa1b2 = A * a1b2;
            float G = Aa1b2 - Z;
            float H = fmaf(-d * ct2, cp1, A * a2b1);
            float D = fmaf(E, F, G * H * p2);
            float num = fmaf(X - Y, F, -(Aa1b2 + Z) * H * p2);

            row[a] = __float2half(__fdividef(num, D));
        }
    }
    __syncthreads();   // Rs complete; all warps aligned entering GEMM

    // ---- Phase 2: GEMM ----
    int wid = tid >> 5, lane = tid & 31;
    int wm = (wid >> 1) * 64;                  // 0,64,128,192
    int wn = (wid & 1) * 32;                   // 0 (trace 0) or 32 (trace 1)
    int r8 = lane >> 3, i8 = lane & 7;
    int a_frow = wm + (r8 & 1) * 8 + i8;       // + mt*16
    int a_fcol = (r8 >> 1) * 8;                // + kk*16
    int b_fkrow = (r8 & 1) * 8 + i8;           // + step*32 + kk*16
    int b_fncol = wn + (r8 >> 1) * 8;          // + pair*16

    uint32_t sAf = smaddr(&Ah[a_frow * APITCH + a_fcol]);
    uint32_t sRf = smaddr(&Rs[b_fkrow * RPITCH + b_fncol]);

    float acc[4][4][4];
#pragma unroll
    for (int mt = 0; mt < 4; mt++)
#pragma unroll
        for (int nt = 0; nt < 4; nt++)
#pragma unroll
            for (int e = 0; e < 4; e++) acc[mt][nt][e] = 0.f;

    const int NSTEP = KPAD / ABK;  // 8

#pragma unroll
    for (int s = 0; s < NSTEP; s++) {
        // ensure stage s's group has drained
        if (s < NSTEP - 1) { CP_WAIT(1); } else { CP_WAIT(0); }
        __syncthreads();   // also proves step s-1 readers of buffer (s+2)%3 done

        // refill stage s+2 into buffer (s+2)%3 (compile-time constant)
        if (s + 2 < NSTEP) {
            const int nb = (s + 2) % 3;
            const int k0 = (s + 2) * ABK;
#pragma unroll
            for (int c = 0; c < 4; c++)
                CP16(sA + nb * (ASTG * 2) + c * 16, pW + k0 + c * 8);
            CP_COMMIT();
        }

        const int buf = s % 3;                 // compile-time (full unroll)
        uint32_t aBase = sAf + buf * (ASTG * 2);
        uint32_t bRow  = sRf + s * ABK * (RPITCH * 2);

#pragma unroll
        for (int kk = 0; kk < 2; kk++) {
            uint32_t bhf[4][2];
#pragma unroll
            for (int pair = 0; pair < 2; pair++) {
                uint32_t t4[4];
                ldsm4t(t4, bRow + kk * 16 * (RPITCH * 2) + pair * 32);
                bhf[pair * 2][0] = t4[0]; bhf[pair * 2][1] = t4[1];
                bhf[pair * 2 + 1][0] = t4[2]; bhf[pair * 2 + 1][1] = t4[3];
            }
#pragma unroll
            for (int mt = 0; mt < 4; mt++) {
                uint32_t ahf[4];
                ldsm4(ahf, aBase + mt * 16 * (APITCH * 2) + kk * 32);
#pragma unroll
                for (int nt = 0; nt < 4; nt++) {
                    mma16816(acc[mt][nt], ahf, bhf[nt]);
                }
            }
        }
    }

    // ---- epilogue: out[t, l, a] ----
#pragma unroll
    for (int mt = 0; mt < 4; mt++) {
#pragma unroll
        for (int nt = 0; nt < 4; nt++) {
            int l0 = wm + mt * 16 + (lane >> 2);
            int n0 = wn + nt * 8 + (lane & 3) * 2;
            int j  = n0 >> 5;
            int ab = n0 & 31;
            int t  = t0 + j;
#pragma unroll
            for (int e = 0; e < 4; e++) {
                int l = l0 + (e >> 1) * 8;
                int a = ab + (e & 1);
                if (l < L_LAYERS && a < N_THETA) {
                    out[t * (L_LAYERS * N_THETA) + l * N_THETA + a] = acc[mt][nt][e];
                }
            }
        }
    }
}

extern "C" void kernel_launch(void* const* d_in, const int* in_sizes, int n_in,
                              void* d_out, int out_size) {
    const float* vp      = (const float*)d_in[0];
    const float* vs      = (const float*)d_in[1];
    const float* rho     = (const float*)d_in[2];
    const float* theta   = (const float*)d_in[3];
    const float* wavemat = (const float*)d_in[4];
    float* out = (float*)d_out;

    cudaFuncSetAttribute(zoe_fused, cudaFuncAttributeMaxDynamicSharedMemorySize,
                         SMEM_BYTES);

    zoe_wsplit<<<256, 256>>>(wavemat);
    zoe_fused<<<N_TRACES / 2, 256, SMEM_BYTES>>>(vp, vs, rho, theta, out);
}